// round 4
// baseline (speedup 1.0000x reference)
#include <cuda_runtime.h>
#include <cstddef>

#define IMG_H 512
#define IMG_W 512
#define IMGF  (IMG_H * IMG_W * 3)   // floats per batch image = 786432
#define TILE_W 64
#define TILE_H 32
#define RSTRIDE 204                  // floats per smem row (200 used + pad)
#define NROWS 34                     // TILE_H + 2 halo rows
#define NV 50                        // float4 stores per smem row

__constant__ float c_w[81];   // [ky][kx][ci][co] HWIO
__constant__ float c_b[3];

__device__ __forceinline__ void load_row(const float* __restrict__ srow,
                                         float f[20], bool zl, bool zr)
{
    const float4* p = (const float4*)srow;
#pragma unroll
    for (int j = 0; j < 5; j++) {
        float4 v = p[j];
        f[4*j+0] = v.x; f[4*j+1] = v.y; f[4*j+2] = v.z; f[4*j+3] = v.w;
    }
    if (zl) { f[1] = 0.f; f[2] = 0.f; f[3] = 0.f; }       // px (w0-1) off-image
    if (zr) { f[16] = 0.f; f[17] = 0.f; f[18] = 0.f; }    // px (w0+64) off-image
}

// Apply one input row with conv-weight-row `wrow` to a 4-px accumulator.
__device__ __forceinline__ void apply_row(const float f[20], float acc[12], const int wrow)
{
#pragma unroll
    for (int x = 0; x < 4; x++) {
#pragma unroll
        for (int dx = 0; dx < 3; dx++) {
#pragma unroll
            for (int ci = 0; ci < 3; ci++) {
                const float v = f[3*(x + dx) + ci + 1];
                const int wb = ((wrow*3 + dx)*3 + ci)*3;
                acc[x*3 + 0] += v * c_w[wb + 0];
                acc[x*3 + 1] += v * c_w[wb + 1];
                acc[x*3 + 2] += v * c_w[wb + 2];
            }
        }
    }
}

__global__ __launch_bounds__(256)
void patchenc_v2_kernel(const float* __restrict__ X,
                        const float* __restrict__ pos_emb,
                        float* __restrict__ out)
{
    __shared__ float s[NROWS * RSTRIDE];   // 27744 B

    const int b  = blockIdx.z;
    const int h0 = blockIdx.y * TILE_H;
    const int w0 = blockIdx.x * TILE_W;
    const float* __restrict__ Xb = X + (size_t)b * IMGF;

    // ---- vectorized tile fill: packed rows, 1-float front pad ----
    // smem float (row*RSTRIDE + s) holds batch-float g0a + (s - 0) where
    // g0a = 3*(gh*512 + w0) - 4  (16B-aligned floor of channel0 of px (w0-1)).
    for (int p = threadIdx.x; p < NROWS * NV; p += 256) {
        const int row = p / NV;
        const int j   = p - row * NV;
        const int gh  = h0 - 1 + row;
        const int gidx = 3 * (gh * IMG_W + w0) - 4 + 4 * j;
        float4 v = make_float4(0.f, 0.f, 0.f, 0.f);
        if (gidx >= 0 && gidx + 3 < IMGF)
            v = *(const float4*)(Xb + gidx);
        *(float4*)&s[row * RSTRIDE + 4*j] = v;
    }
    __syncthreads();

    const int txq = threadIdx.x & 15;     // 0..15 -> x quad
    const int tyq = threadIdx.x >> 4;     // 0..15 -> y pair
    const bool zl = (blockIdx.x == 0) && (txq == 0);
    const bool zr = (blockIdx.x == (IMG_W/TILE_W - 1)) && (txq == 15);

    float acc0[12], acc1[12];
#pragma unroll
    for (int x = 0; x < 4; x++) {
#pragma unroll
        for (int c = 0; c < 3; c++) { acc0[x*3+c] = c_b[c]; acc1[x*3+c] = c_b[c]; }
    }

    // smem rows needed: local rows 2*tyq .. 2*tyq+3
    const float* rbase = &s[(2*tyq) * RSTRIDE + 12*txq];
    float f[20];

    load_row(rbase + 0*RSTRIDE, f, zl, zr);
    apply_row(f, acc0, 0);
    load_row(rbase + 1*RSTRIDE, f, zl, zr);
    apply_row(f, acc0, 1);
    apply_row(f, acc1, 0);
    load_row(rbase + 2*RSTRIDE, f, zl, zr);
    apply_row(f, acc0, 2);
    apply_row(f, acc1, 1);
    load_row(rbase + 3*RSTRIDE, f, zl, zr);
    apply_row(f, acc1, 2);

    // ---- PE add + permuted vector store ----
    const int gw0 = w0 + 4*txq;                    // multiple of 4
    const size_t out_b = (size_t)b * (1024 * 768);

#pragma unroll
    for (int k = 0; k < 2; k++) {
        const float* acc = (k == 0) ? acc0 : acc1;
        const int gh = h0 + 2*tyq + k;

        const int nf = (gh >> 2) * 128 + (gw0 >> 2);
        const float4* pe = (const float4*)(pos_emb + nf * 48 + (gh & 3) * 12);
        float4 p0 = pe[0], p1 = pe[1], p2 = pe[2];

        const int np = (gh >> 4) * 32 + (gw0 >> 4);
        float4* o = (float4*)(out + out_b + (size_t)np * 768 + (gh & 15) * 48 + (gw0 & 15) * 3);
        o[0] = make_float4(acc[0] + p0.x, acc[1]  + p0.y, acc[2]  + p0.z, acc[3]  + p0.w);
        o[1] = make_float4(acc[4] + p1.x, acc[5]  + p1.y, acc[6]  + p1.z, acc[7]  + p1.w);
        o[2] = make_float4(acc[8] + p2.x, acc[9]  + p2.y, acc[10] + p2.z, acc[11] + p2.w);
    }
}

extern "C" void kernel_launch(void* const* d_in, const int* in_sizes, int n_in,
                              void* d_out, int out_size)
{
    const float* X  = (const float*)d_in[0];
    const float* Kw = (const float*)d_in[1];   // 81 floats, HWIO
    const float* Bb = (const float*)d_in[2];   // 3 floats
    const float* PE = (const float*)d_in[3];   // 16384 x 48

    cudaMemcpyToSymbolAsync(c_w, Kw, 81 * sizeof(float), 0, cudaMemcpyDeviceToDevice, 0);
    cudaMemcpyToSymbolAsync(c_b, Bb, 3 * sizeof(float), 0, cudaMemcpyDeviceToDevice, 0);

    dim3 grid(IMG_W / TILE_W, IMG_H / TILE_H, 32);
    patchenc_v2_kernel<<<grid, 256>>>(X, PE, (float*)d_out);
}

// round 7
// speedup vs baseline: 1.2603x; 1.2603x over previous
#include <cuda_runtime.h>
#include <cstddef>

#define IMG_H 512
#define IMG_W 512
#define IMGF  (IMG_H * IMG_W * 3)   // floats per batch image = 786432
#define TILE_W 64
#define TILE_H 32

__constant__ float c_w[81];   // [ky][kx][ci][co] HWIO
__constant__ float c_b[3];

// Load one 20-float window row straight from global (16B-aligned),
// with SAME-padding fixups. rvalid=false -> all zeros.
__device__ __forceinline__ void load_row_g(const float* __restrict__ Xb,
                                           int row_off,   // float index of f[0]
                                           bool rvalid, bool zl, bool zr,
                                           float f[20])
{
#pragma unroll
    for (int j = 0; j < 5; j++) {
        float4 v = make_float4(0.f, 0.f, 0.f, 0.f);
        const int g = row_off + 4 * j;
        if (rvalid && g >= 0 && g + 3 < IMGF)
            v = *(const float4*)(Xb + g);
        f[4*j+0] = v.x; f[4*j+1] = v.y; f[4*j+2] = v.z; f[4*j+3] = v.w;
    }
    if (zl) { f[1]  = 0.f; f[2]  = 0.f; f[3]  = 0.f; }   // px gw0-1 off-image
    if (zr) { f[16] = 0.f; f[17] = 0.f; f[18] = 0.f; }   // px gw0+4 off-image
}

// Apply one input row with conv-weight-row `wrow` to a 4-px accumulator.
__device__ __forceinline__ void apply_row(const float f[20], float acc[12], const int wrow)
{
#pragma unroll
    for (int x = 0; x < 4; x++) {
#pragma unroll
        for (int dx = 0; dx < 3; dx++) {
#pragma unroll
            for (int ci = 0; ci < 3; ci++) {
                const float v = f[3*(x + dx) + ci + 1];
                const int wb = ((wrow*3 + dx)*3 + ci)*3;
                acc[x*3 + 0] += v * c_w[wb + 0];
                acc[x*3 + 1] += v * c_w[wb + 1];
                acc[x*3 + 2] += v * c_w[wb + 2];
            }
        }
    }
}

__global__ __launch_bounds__(256, 4)
void patchenc_v3_kernel(const float* __restrict__ X,
                        const float* __restrict__ pos_emb,
                        float* __restrict__ out)
{
    const int b  = blockIdx.z;
    const int h0 = blockIdx.y * TILE_H;
    const int w0 = blockIdx.x * TILE_W;
    const float* __restrict__ Xb = X + (size_t)b * IMGF;

    const int txq = threadIdx.x & 15;     // 0..15 -> x quad (gw0 = w0 + 4*txq)
    const int tyq = threadIdx.x >> 4;     // 0..15 -> y pair (gh0 = h0 + 2*tyq)
    const int gh0 = h0 + 2 * tyq;

    const bool zl = (w0 == 0) && (txq == 0);
    const bool zr = (w0 == IMG_W - TILE_W) && (txq == 15);

    // float offset of f[0] for image row r: 3*(r*512 + w0) + 12*txq - 4
    const int base_off = 3 * w0 + 12 * txq - 4;
    const int ROWF = 3 * IMG_W;

    float acc0[12], acc1[12];
#pragma unroll
    for (int x = 0; x < 4; x++) {
#pragma unroll
        for (int c = 0; c < 3; c++) { acc0[x*3+c] = c_b[c]; acc1[x*3+c] = c_b[c]; }
    }

    float f[20];

    // rows gh0-1 .. gh0+2 streamed through one window
    {
        const int r = gh0 - 1;
        load_row_g(Xb, base_off + r * ROWF, r >= 0, zl, zr, f);
        apply_row(f, acc0, 0);
    }
    {
        const int r = gh0;
        load_row_g(Xb, base_off + r * ROWF, true, zl, zr, f);
        apply_row(f, acc0, 1);
        apply_row(f, acc1, 0);
    }
    {
        const int r = gh0 + 1;
        load_row_g(Xb, base_off + r * ROWF, true, zl, zr, f);
        apply_row(f, acc0, 2);
        apply_row(f, acc1, 1);
    }
    {
        const int r = gh0 + 2;
        load_row_g(Xb, base_off + r * ROWF, r < IMG_H, zl, zr, f);
        apply_row(f, acc1, 2);
    }

    // ---- PE add + permuted vector store ----
    const int gw0 = w0 + 4 * txq;                  // multiple of 4
    const size_t out_b = (size_t)b * (1024 * 768);

#pragma unroll
    for (int k = 0; k < 2; k++) {
        const float* acc = (k == 0) ? acc0 : acc1;
        const int gh = gh0 + k;

        const int nf = (gh >> 2) * 128 + (gw0 >> 2);
        const float4* pe = (const float4*)(pos_emb + nf * 48 + (gh & 3) * 12);
        float4 p0 = pe[0], p1 = pe[1], p2 = pe[2];

        const int np = (gh >> 4) * 32 + (gw0 >> 4);
        float4* o = (float4*)(out + out_b + (size_t)np * 768 + (gh & 15) * 48 + (gw0 & 15) * 3);
        o[0] = make_float4(acc[0] + p0.x, acc[1]  + p0.y, acc[2]  + p0.z, acc[3]  + p0.w);
        o[1] = make_float4(acc[4] + p1.x, acc[5]  + p1.y, acc[6]  + p1.z, acc[7]  + p1.w);
        o[2] = make_float4(acc[8] + p2.x, acc[9]  + p2.y, acc[10] + p2.z, acc[11] + p2.w);
    }
}

extern "C" void kernel_launch(void* const* d_in, const int* in_sizes, int n_in,
                              void* d_out, int out_size)
{
    const float* X  = (const float*)d_in[0];
    const float* Kw = (const float*)d_in[1];   // 81 floats, HWIO
    const float* Bb = (const float*)d_in[2];   // 3 floats
    const float* PE = (const float*)d_in[3];   // 16384 x 48

    cudaMemcpyToSymbolAsync(c_w, Kw, 81 * sizeof(float), 0, cudaMemcpyDeviceToDevice, 0);
    cudaMemcpyToSymbolAsync(c_b, Bb, 3 * sizeof(float), 0, cudaMemcpyDeviceToDevice, 0);

    dim3 grid(IMG_W / TILE_W, IMG_H / TILE_H, 32);
    patchenc_v3_kernel<<<grid, 256>>>(X, PE, (float*)d_out);
}